// round 14
// baseline (speedup 1.0000x reference)
#include <cuda_runtime.h>
#include <cuda_bf16.h>
#include <math.h>
#include <stdint.h>

#define N_PTS 8192
#define M_PTS 2048
#define K_LAST 10
#define VARS 3

typedef unsigned long long u64;

// ---------------- packed f32x2 helpers ----------------
__device__ __forceinline__ u64 pk2(float lo, float hi) {
    u64 r; asm("mov.b64 %0,{%1,%2};" : "=l"(r) : "f"(lo), "f"(hi)); return r;
}
__device__ __forceinline__ void unpk2(u64 v, float& lo, float& hi) {
    asm("mov.b64 {%0,%1},%2;" : "=f"(lo), "=f"(hi) : "l"(v));
}
__device__ __forceinline__ u64 f2fma(u64 a, u64 b, u64 c) {
    u64 d; asm("fma.rn.f32x2 %0,%1,%2,%3;" : "=l"(d) : "l"(a), "l"(b), "l"(c)); return d;
}
__device__ __forceinline__ u64 f2mul(u64 a, u64 b) {
    u64 d; asm("mul.rn.f32x2 %0,%1,%2;" : "=l"(d) : "l"(a), "l"(b)); return d;
}
__device__ __forceinline__ u64 dup2(float x) { return pk2(x, x); }

__device__ __forceinline__ float gelu(float x) {
    return 0.5f * x * (1.0f + erff(x * 0.70710678118654752f));
}

// packed GELU (A&S 7.1.26 erf, abs err <= 1.5e-7)
__device__ __forceinline__ u64 gelu2(u64 x) {
    u64 ax = x & 0x7FFFFFFF7FFFFFFFULL;
    u64 z  = f2mul(ax, dup2(0.70710678118654752f));
    u64 den = f2fma(z, dup2(0.3275911f), dup2(1.0f));
    float dl, dh, rl, rh;
    unpk2(den, dl, dh);
    asm("rcp.approx.f32 %0,%1;" : "=f"(rl) : "f"(dl));
    asm("rcp.approx.f32 %0,%1;" : "=f"(rh) : "f"(dh));
    u64 t = pk2(rl, rh);
    u64 z2 = f2mul(z, z);
    u64 m  = f2mul(z2, dup2(-1.4426950408889634f));
    float ml, mh, el, eh;
    unpk2(m, ml, mh);
    asm("ex2.approx.f32 %0,%1;" : "=f"(el) : "f"(ml));
    asm("ex2.approx.f32 %0,%1;" : "=f"(eh) : "f"(mh));
    u64 e = pk2(el, eh);
    u64 p = f2fma(t, dup2(1.061405429f), dup2(-1.453152027f));
    p = f2fma(p, t, dup2(1.421413741f));
    p = f2fma(p, t, dup2(-0.284496736f));
    p = f2fma(p, t, dup2(0.254829592f));
    p = f2mul(p, t);
    u64 np = p ^ 0x8000000080000000ULL;
    u64 u  = f2fma(np, e, dup2(1.0f));
    u64 E  = u | (x & 0x8000000080000000ULL);
    u64 h  = f2fma(E, dup2(0.5f), dup2(0.5f));
    return f2mul(x, h);
}

// pack two floats to bf16x2 (a -> low 16 bits, b -> high)
__device__ __forceinline__ uint32_t pack_bf16(float a, float b) {
    uint32_t r; asm("cvt.rn.bf16x2.f32 %0, %1, %2;" : "=r"(r) : "f"(b), "f"(a));
    return r;
}
// split f32 pair into (hi bf16x2, lo bf16x2)
__device__ __forceinline__ void split_pack(float f0, float f1, uint32_t& hi, uint32_t& lo) {
    hi = pack_bf16(f0, f1);
    float h0 = __uint_as_float(hi << 16);
    float h1 = __uint_as_float(hi & 0xFFFF0000u);
    lo = pack_bf16(f0 - h0, f1 - h1);
}

// m16n8k16 bf16 MMA, D (f32) accumulate in place
__device__ __forceinline__ void mma16816(float* d, const uint32_t* a, uint32_t b0, uint32_t b1) {
    asm volatile(
        "mma.sync.aligned.m16n8k16.row.col.f32.bf16.bf16.f32 "
        "{%0,%1,%2,%3}, {%4,%5,%6,%7}, {%8,%9}, {%0,%1,%2,%3};"
        : "+f"(d[0]), "+f"(d[1]), "+f"(d[2]), "+f"(d[3])
        : "r"(a[0]), "r"(a[1]), "r"(a[2]), "r"(a[3]), "r"(b0), "r"(b1));
}

// ---------------- scratch ----------------
__device__ float g_f0[VARS * N_PTS * 32];
__device__ float g_acc[VARS * N_PTS * 32];
__device__ uint8_t g_blob[2][51200];
// interleaved blob: per set 512B, lane entry = uint4 {bh0, bh1, bl0, bl1}
#define BL1 0        // 30 sets * 512
#define BL2 15360    // 50 sets * 512
#define BL3 40960    // 20 sets * 512
#define BLOB_BYTES 51200

// ---------------- fused weight prep (both phases, all layers) ----------------
__global__ void prep_all_kernel(const float* __restrict__ W10, const float* __restrict__ W11,
                                const float* __restrict__ W12,
                                const float* __restrict__ W20, const float* __restrict__ W21,
                                const float* __restrict__ W22,
                                uint8_t* __restrict__ blob0, uint8_t* __restrict__ blob1) {
    int idx = blockIdx.x * 256 + threadIdx.x;
    if (idx >= 2 * 100 * 32) return;
    int lane = idx & 31;
    int set = (idx >> 5) % 100;
    int phase = (idx >> 5) / 100;
    uint8_t* blob = phase ? blob1 : blob0;

    const float* W; int NT, N, Kreal, sl, ob;
    if (set < 30)      { W = phase ? W20 : W10; NT = 10; N = 80; Kreal = 36; sl = set;      ob = BL1; }
    else if (set < 80) { W = phase ? W21 : W11; NT = 10; N = 80; Kreal = 80; sl = set - 30; ob = BL2; }
    else               { W = phase ? W22 : W12; NT = 4;  N = 32; Kreal = 80; sl = set - 80; ob = BL3; }

    int kt = sl / NT, nt = sl - kt * NT;
    int n = nt * 8 + (lane >> 2);
    int k0 = kt * 16 + 2 * (lane & 3);
    float v[4];
#pragma unroll
    for (int j = 0; j < 4; j++) {
        int k = k0 + (j >> 1) * 8 + (j & 1);
        v[j] = (k < Kreal) ? W[k * N + n] : 0.f;
    }
    uint32_t h0, l0, h1, l1;
    split_pack(v[0], v[1], h0, l0);
    split_pack(v[2], v[3], h1, l1);
    *(uint4*)(blob + ob + (size_t)sl * 512 + lane * 16) = make_uint4(h0, h1, l0, l1);
}

// ---------------- projection MLP ----------------
__global__ void proj_kernel(const float* __restrict__ inp,
                            const float* __restrict__ W0, const float* __restrict__ b0,
                            const float* __restrict__ W1, const float* __restrict__ b1,
                            float* __restrict__ f0) {
    __shared__ float hs[4][64];
    int warp = threadIdx.x >> 5, lane = threadIdx.x & 31;
    int pv = blockIdx.x * 4 + warp;
    if (pv >= VARS * N_PTS) return;
    int v = pv / N_PTS, n = pv - v * N_PTS;
    const float* x = inp + n * (VARS * 8) + v * 8;
    float xr[8];
#pragma unroll
    for (int i = 0; i < 8; i++) xr[i] = x[i];
    float a0 = b0[lane], a1 = b0[lane + 32];
#pragma unroll
    for (int i = 0; i < 8; i++) {
        a0 = fmaf(xr[i], W0[i * 64 + lane], a0);
        a1 = fmaf(xr[i], W0[i * 64 + lane + 32], a1);
    }
    hs[warp][lane]      = gelu(a0);
    hs[warp][lane + 32] = gelu(a1);
    __syncwarp();
    float acc = b1[lane];
#pragma unroll
    for (int h = 0; h < 64; h++) acc = fmaf(hs[warp][h], W1[h * 32 + lane], acc);
    f0[(size_t)pv * 32 + lane] = acc;
}

// ---------------- HMMA edge MLP ----------------
// Block: 128 threads = 4 warps; each warp processes 4 tiles of 16 edges
// (256 edges/block -> blob staging amortized 2x vs R12).
// x row: pos 0..3, f 4..35, zeros 36..47 (K=48, 3 k-tiles).
#define TPB 128
#define TILES_PW 4
#define SM_BS0   51200
#define SM_BS1   51520
#define SM_BS2   51840
#define SM_XST   51968          // + warp*3072 (16 rows x 48 floats)
#define SM_SEG   64256          // + warp*64
#define SMEM_BYTES 64512

template <int MODE>
__global__ void __launch_bounds__(TPB, 3)
edge_mma_kernel(const uint8_t* __restrict__ blob,
                const float* __restrict__ b0g, const float* __restrict__ b1g,
                const float* __restrict__ b2g,
                const float* __restrict__ grid_in, const float* __restrict__ grid_out,
                const float* __restrict__ fsrc,
                const int* __restrict__ idxA, const int* __restrict__ idxB,
                float* __restrict__ outbuf, int E) {
    extern __shared__ __align__(16) uint8_t sm[];
    int tid = threadIdx.x;
    int warp = tid >> 5, lane = tid & 31;
    int g = lane >> 2;          // row group 0..7
    int t = lane & 3;           // thread-in-group
    int v = blockIdx.y;

    // stage blob + biases
    {
        const uint4* src = (const uint4*)blob;
        uint4* dst = (uint4*)sm;
        for (int i = tid; i < BLOB_BYTES / 16; i += TPB) dst[i] = src[i];
        float* bs0 = (float*)(sm + SM_BS0);
        float* bs1 = (float*)(sm + SM_BS1);
        float* bs2 = (float*)(sm + SM_BS2);
        if (tid < 80) { bs0[tid] = b0g[tid]; bs1[tid] = b1g[tid]; }
        if (tid < 32) bs2[tid] = b2g[tid];
    }
    __syncthreads();

    float* xst = (float*)(sm + SM_XST + warp * 3072);
    int*   seg_sh = (int*)(sm + SM_SEG + warp * 64);
    const float* bs0 = (const float*)(sm + SM_BS0);
    const float* bs1 = (const float*)(sm + SM_BS1);
    const float* bs2 = (const float*)(sm + SM_BS2);

#pragma unroll 1
    for (int mt = 0; mt < TILES_PW; mt++) {
        int tileBase = blockIdx.x * (TPB * 2) + warp * (16 * TILES_PW) + mt * 16;

        // ---- gather: 2 lanes per edge ----
        {
            int el = lane & 15, half = lane >> 4;
            int e = tileBase + el;
            bool gv = e < E;
            int ee = gv ? e : 0;
            int jn = idxA[ee];
            int sg = (MODE == 0) ? idxB[ee] : ee / K_LAST;
            float* xrow = xst + el * 48;
            if (half == 0) {
                seg_sh[el] = gv ? sg : -1;
                float p0 = 0, p1 = 0, p2 = 0, p3 = 0;
                if (gv) {
                    p0 = grid_in[2 * jn]; p1 = grid_in[2 * jn + 1];
                    if (MODE == 0) { p2 = grid_in[2 * sg];  p3 = grid_in[2 * sg + 1]; }
                    else           { p2 = grid_out[2 * sg]; p3 = grid_out[2 * sg + 1]; }
                }
                xrow[0] = p0; xrow[1] = p1; xrow[2] = p2; xrow[3] = p3;
            }
            const float4* fp = (const float4*)(fsrc + ((size_t)v * N_PTS + jn) * 32 + half * 16);
            float4* xd = (float4*)(xrow + 4 + 16 * half);
            xd[0] = fp[0]; xd[1] = fp[1]; xd[2] = fp[2]; xd[3] = fp[3];
            if (half == 1) {
                float4 z = make_float4(0.f, 0.f, 0.f, 0.f);
                float4* zz = (float4*)(xrow + 36);
                zz[0] = z; zz[1] = z; zz[2] = z;
            }
        }
        __syncwarp();

        // ---- A1 fragments from x stage (3 k-tiles of 16) ----
        uint32_t a1h[3][4], a1l[3][4];
#pragma unroll
        for (int kt = 0; kt < 3; kt++) {
#pragma unroll
            for (int rr = 0; rr < 4; rr++) {
                int row = g + (rr & 1) * 8;
                int col = 16 * kt + 2 * t + (rr >> 1) * 8;
                u64 pv_ = *(const u64*)(xst + row * 48 + col);
                float f0, f1; unpk2(pv_, f0, f1);
                split_pack(f0, f1, a1h[kt][rr], a1l[kt][rr]);
            }
        }

        // ---- layer 1: K=48, N=80 (10 n-tiles), 1 LDS.128 per (kt,nt) ----
        float d1[10][4];
#pragma unroll
        for (int nt = 0; nt < 10; nt++) {
            float* d = d1[nt];
            d[0] = 0.f; d[1] = 0.f; d[2] = 0.f; d[3] = 0.f;
#pragma unroll
            for (int kt = 0; kt < 3; kt++) {
                int set = kt * 10 + nt;
                uint4 q = *(const uint4*)(sm + BL1 + (size_t)set * 512 + lane * 16);
                mma16816(d, a1h[kt], q.x, q.y);
                mma16816(d, a1h[kt], q.z, q.w);
                mma16816(d, a1l[kt], q.x, q.y);
            }
        }

        // ---- epilogue 1: bias + gelu + split -> A2 fragments ----
        uint32_t a2h[5][4], a2l[5][4];
#pragma unroll
        for (int m = 0; m < 5; m++) {
            int j0 = 2 * m, j1 = 2 * m + 1;
            float bb0, bb1, bb2, bb3;
            unpk2(*(const u64*)(bs0 + 8 * j0 + 2 * t), bb0, bb1);
            unpk2(*(const u64*)(bs0 + 8 * j1 + 2 * t), bb2, bb3);
            float q0, q1;
            unpk2(gelu2(pk2(d1[j0][0] + bb0, d1[j0][1] + bb1)), q0, q1);
            split_pack(q0, q1, a2h[m][0], a2l[m][0]);
            unpk2(gelu2(pk2(d1[j0][2] + bb0, d1[j0][3] + bb1)), q0, q1);
            split_pack(q0, q1, a2h[m][1], a2l[m][1]);
            unpk2(gelu2(pk2(d1[j1][0] + bb2, d1[j1][1] + bb3)), q0, q1);
            split_pack(q0, q1, a2h[m][2], a2l[m][2]);
            unpk2(gelu2(pk2(d1[j1][2] + bb2, d1[j1][3] + bb3)), q0, q1);
            split_pack(q0, q1, a2h[m][3], a2l[m][3]);
        }

        // ---- layer 2: K=80, N=80 ----
        float d2[10][4];
#pragma unroll
        for (int nt = 0; nt < 10; nt++) {
            float* d = d2[nt];
            d[0] = 0.f; d[1] = 0.f; d[2] = 0.f; d[3] = 0.f;
#pragma unroll
            for (int kt = 0; kt < 5; kt++) {
                int set = kt * 10 + nt;
                uint4 q = *(const uint4*)(sm + BL2 + (size_t)set * 512 + lane * 16);
                mma16816(d, a2h[kt], q.x, q.y);
                mma16816(d, a2h[kt], q.z, q.w);
                mma16816(d, a2l[kt], q.x, q.y);
            }
        }

        // ---- epilogue 2 -> A3 fragments ----
        uint32_t a3h[5][4], a3l[5][4];
#pragma unroll
        for (int m = 0; m < 5; m++) {
            int j0 = 2 * m, j1 = 2 * m + 1;
            float bb0, bb1, bb2, bb3;
            unpk2(*(const u64*)(bs1 + 8 * j0 + 2 * t), bb0, bb1);
            unpk2(*(const u64*)(bs1 + 8 * j1 + 2 * t), bb2, bb3);
            float q0, q1;
            unpk2(gelu2(pk2(d2[j0][0] + bb0, d2[j0][1] + bb1)), q0, q1);
            split_pack(q0, q1, a3h[m][0], a3l[m][0]);
            unpk2(gelu2(pk2(d2[j0][2] + bb0, d2[j0][3] + bb1)), q0, q1);
            split_pack(q0, q1, a3h[m][1], a3l[m][1]);
            unpk2(gelu2(pk2(d2[j1][0] + bb2, d2[j1][1] + bb3)), q0, q1);
            split_pack(q0, q1, a3h[m][2], a3l[m][2]);
            unpk2(gelu2(pk2(d2[j1][2] + bb2, d2[j1][3] + bb3)), q0, q1);
            split_pack(q0, q1, a3h[m][3], a3l[m][3]);
        }

        // ---- layer 3: K=80, N=32 (4 n-tiles) ----
        float d3[4][4];
#pragma unroll
        for (int nt = 0; nt < 4; nt++) {
            float* d = d3[nt];
            d[0] = 0.f; d[1] = 0.f; d[2] = 0.f; d[3] = 0.f;
#pragma unroll
            for (int kt = 0; kt < 5; kt++) {
                int set = kt * 4 + nt;
                uint4 q = *(const uint4*)(sm + BL3 + (size_t)set * 512 + lane * 16);
                mma16816(d, a3h[kt], q.x, q.y);
                mma16816(d, a3h[kt], q.z, q.w);
                mma16816(d, a3l[kt], q.x, q.y);
            }
        }

        // ---- epilogue 3: bias + scatter (rows g and g+8), pointers hoisted ----
        {
            int sg0 = seg_sh[g], sg1 = seg_sh[g + 8];
            float scale = (MODE == 0) ? 1.0f : 0.1f;
            float* dst0 = nullptr; float* dst1 = nullptr;
            if (MODE == 0) {
                if (sg0 >= 0) dst0 = outbuf + ((size_t)v * N_PTS + sg0) * 32;
                if (sg1 >= 0) dst1 = outbuf + ((size_t)v * N_PTS + sg1) * 32;
            } else {
                if (sg0 >= 0) dst0 = outbuf + (size_t)sg0 * (VARS * 32) + v * 32;
                if (sg1 >= 0) dst1 = outbuf + (size_t)sg1 * (VARS * 32) + v * 32;
            }
#pragma unroll
            for (int nt = 0; nt < 4; nt++) {
                float bb0, bb1;
                unpk2(*(const u64*)(bs2 + 8 * nt + 2 * t), bb0, bb1);
                int c0 = 8 * nt + 2 * t;
                if (dst0) {
                    atomicAdd(dst0 + c0,     (d3[nt][0] + bb0) * scale);
                    atomicAdd(dst0 + c0 + 1, (d3[nt][1] + bb1) * scale);
                }
                if (dst1) {
                    atomicAdd(dst1 + c0,     (d3[nt][2] + bb0) * scale);
                    atomicAdd(dst1 + c0 + 1, (d3[nt][3] + bb1) * scale);
                }
            }
        }
        __syncwarp();
    }
}

// f1 = segment_sum * inv_count + f0 (in place)
__global__ void f1_kernel(float* __restrict__ f0, const float* __restrict__ acc,
                          const int* __restrict__ counts) {
    int idx = blockIdx.x * 256 + threadIdx.x;
    if (idx >= VARS * N_PTS * 32) return;
    int n = (idx >> 5) % N_PTS;
    int c = counts[n];
    float inv = 1.0f / (float)(c > 1 ? c : 1);
    f0[idx] = fmaf(acc[idx], inv, f0[idx]);
}

extern "C" void kernel_launch(void* const* d_in, const int* in_sizes, int n_in,
                              void* d_out, int out_size) {
    const float* inp   = (const float*)d_in[0];
    const float* gin   = (const float*)d_in[1];
    const float* gout  = (const float*)d_in[2];
    const float* pW0   = (const float*)d_in[3];
    const float* pb0   = (const float*)d_in[4];
    const float* pW1   = (const float*)d_in[5];
    const float* pb1   = (const float*)d_in[6];
    const float* i0W0  = (const float*)d_in[7];
    const float* i0b0  = (const float*)d_in[8];
    const float* i0W1  = (const float*)d_in[9];
    const float* i0b1  = (const float*)d_in[10];
    const float* i0W2  = (const float*)d_in[11];
    const float* i0b2  = (const float*)d_in[12];
    const float* i1W0  = (const float*)d_in[13];
    const float* i1b0  = (const float*)d_in[14];
    const float* i1W1  = (const float*)d_in[15];
    const float* i1b1  = (const float*)d_in[16];
    const float* i1W2  = (const float*)d_in[17];
    const float* i1b2  = (const float*)d_in[18];
    const int* nbr_index  = (const int*)d_in[19];
    const int* nbr_seg    = (const int*)d_in[20];
    const int* nbr_counts = (const int*)d_in[21];
    const int* nbr_last   = (const int*)d_in[22];
    int E = in_sizes[19];

    float *f0, *acc;
    uint8_t* blob;
    cudaGetSymbolAddress((void**)&f0,   g_f0);
    cudaGetSymbolAddress((void**)&acc,  g_acc);
    cudaGetSymbolAddress((void**)&blob, g_blob);
    uint8_t* blob0 = blob;
    uint8_t* blob1 = blob + BLOB_BYTES;

    cudaMemsetAsync(acc, 0, sizeof(float) * VARS * N_PTS * 32);
    cudaMemsetAsync(d_out, 0, sizeof(float) * (size_t)out_size);

    prep_all_kernel<<<(2 * 100 * 32 + 255) / 256, 256>>>(i0W0, i0W1, i0W2,
                                                         i1W0, i1W1, i1W2, blob0, blob1);

    proj_kernel<<<(VARS * N_PTS + 3) / 4, 128>>>(inp, pW0, pb0, pW1, pb1, f0);

    cudaFuncSetAttribute(edge_mma_kernel<0>, cudaFuncAttributeMaxDynamicSharedMemorySize, SMEM_BYTES);
    cudaFuncSetAttribute(edge_mma_kernel<1>, cudaFuncAttributeMaxDynamicSharedMemorySize, SMEM_BYTES);

    const int EPB = TPB * 2;   // 256 edges per block
    dim3 g1((unsigned)((E + EPB - 1) / EPB), VARS);
    edge_mma_kernel<0><<<g1, TPB, SMEM_BYTES>>>(blob0, i0b0, i0b1, i0b2,
                                                gin, nullptr, f0, nbr_index, nbr_seg, acc, E);

    f1_kernel<<<(VARS * N_PTS * 32 + 255) / 256, 256>>>(f0, acc, nbr_counts);

    int E2 = M_PTS * K_LAST;
    dim3 g2((unsigned)((E2 + EPB - 1) / EPB), VARS);
    edge_mma_kernel<1><<<g2, TPB, SMEM_BYTES>>>(blob1, i1b0, i1b1, i1b2,
                                                gin, gout, f0, nbr_last, nullptr, (float*)d_out, E2);
}

// round 15
// speedup vs baseline: 1.6662x; 1.6662x over previous
#include <cuda_runtime.h>
#include <cuda_bf16.h>
#include <math.h>
#include <stdint.h>

#define N_PTS 8192
#define M_PTS 2048
#define K_LAST 10
#define VARS 3

typedef unsigned long long u64;

// ---------------- packed f32x2 helpers ----------------
__device__ __forceinline__ u64 pk2(float lo, float hi) {
    u64 r; asm("mov.b64 %0,{%1,%2};" : "=l"(r) : "f"(lo), "f"(hi)); return r;
}
__device__ __forceinline__ void unpk2(u64 v, float& lo, float& hi) {
    asm("mov.b64 {%0,%1},%2;" : "=f"(lo), "=f"(hi) : "l"(v));
}
__device__ __forceinline__ u64 f2fma(u64 a, u64 b, u64 c) {
    u64 d; asm("fma.rn.f32x2 %0,%1,%2,%3;" : "=l"(d) : "l"(a), "l"(b), "l"(c)); return d;
}
__device__ __forceinline__ u64 f2mul(u64 a, u64 b) {
    u64 d; asm("mul.rn.f32x2 %0,%1,%2;" : "=l"(d) : "l"(a), "l"(b)); return d;
}
__device__ __forceinline__ u64 dup2(float x) { return pk2(x, x); }

__device__ __forceinline__ float gelu(float x) {
    return 0.5f * x * (1.0f + erff(x * 0.70710678118654752f));
}

// packed GELU (A&S 7.1.26 erf, abs err <= 1.5e-7)
__device__ __forceinline__ u64 gelu2(u64 x) {
    u64 ax = x & 0x7FFFFFFF7FFFFFFFULL;
    u64 z  = f2mul(ax, dup2(0.70710678118654752f));
    u64 den = f2fma(z, dup2(0.3275911f), dup2(1.0f));
    float dl, dh, rl, rh;
    unpk2(den, dl, dh);
    asm("rcp.approx.f32 %0,%1;" : "=f"(rl) : "f"(dl));
    asm("rcp.approx.f32 %0,%1;" : "=f"(rh) : "f"(dh));
    u64 t = pk2(rl, rh);
    u64 z2 = f2mul(z, z);
    u64 m  = f2mul(z2, dup2(-1.4426950408889634f));
    float ml, mh, el, eh;
    unpk2(m, ml, mh);
    asm("ex2.approx.f32 %0,%1;" : "=f"(el) : "f"(ml));
    asm("ex2.approx.f32 %0,%1;" : "=f"(eh) : "f"(mh));
    u64 e = pk2(el, eh);
    u64 p = f2fma(t, dup2(1.061405429f), dup2(-1.453152027f));
    p = f2fma(p, t, dup2(1.421413741f));
    p = f2fma(p, t, dup2(-0.284496736f));
    p = f2fma(p, t, dup2(0.254829592f));
    p = f2mul(p, t);
    u64 np = p ^ 0x8000000080000000ULL;
    u64 u  = f2fma(np, e, dup2(1.0f));
    u64 E  = u | (x & 0x8000000080000000ULL);
    u64 h  = f2fma(E, dup2(0.5f), dup2(0.5f));
    return f2mul(x, h);
}

// pack two floats to bf16x2 (a -> low 16 bits, b -> high)
__device__ __forceinline__ uint32_t pack_bf16(float a, float b) {
    uint32_t r; asm("cvt.rn.bf16x2.f32 %0, %1, %2;" : "=r"(r) : "f"(b), "f"(a));
    return r;
}
// split f32 pair into (hi bf16x2, lo bf16x2)
__device__ __forceinline__ void split_pack(float f0, float f1, uint32_t& hi, uint32_t& lo) {
    hi = pack_bf16(f0, f1);
    float h0 = __uint_as_float(hi << 16);
    float h1 = __uint_as_float(hi & 0xFFFF0000u);
    lo = pack_bf16(f0 - h0, f1 - h1);
}
__device__ __forceinline__ u64 split_u64(float f0, float f1) {
    uint32_t h, l; split_pack(f0, f1, h, l);
    return (u64)h | ((u64)l << 32);
}

// m16n8k16 bf16 MMA, D (f32) accumulate in place
__device__ __forceinline__ void mma16816(float* d, const uint32_t* a, uint32_t b0, uint32_t b1) {
    asm volatile(
        "mma.sync.aligned.m16n8k16.row.col.f32.bf16.bf16.f32 "
        "{%0,%1,%2,%3}, {%4,%5,%6,%7}, {%8,%9}, {%0,%1,%2,%3};"
        : "+f"(d[0]), "+f"(d[1]), "+f"(d[2]), "+f"(d[3])
        : "r"(a[0]), "r"(a[1]), "r"(a[2]), "r"(a[3]), "r"(b0), "r"(b1));
}

// ---------------- scratch ----------------
__device__ float g_f0[VARS * N_PTS * 32];
__device__ float g_acc[VARS * N_PTS * 32];
__device__ u64   g_fsplit[VARS * N_PTS * 16];  // {hi,lo} bf16x2 per col-pair
__device__ u64   g_psin[N_PTS];                // split input-grid positions
__device__ u64   g_psout[M_PTS];               // split output-grid positions
__device__ uint8_t g_blob[2][51200];
// interleaved blob: per set 512B, lane entry = uint4 {bh0, bh1, bl0, bl1}
#define BL1 0        // 30 sets * 512
#define BL2 15360    // 50 sets * 512
#define BL3 40960    // 20 sets * 512
#define BLOB_BYTES 51200

// ---------------- fused weight prep + split positions ----------------
__global__ void prep_all_kernel(const float* __restrict__ W10, const float* __restrict__ W11,
                                const float* __restrict__ W12,
                                const float* __restrict__ W20, const float* __restrict__ W21,
                                const float* __restrict__ W22,
                                const float* __restrict__ gin, const float* __restrict__ gout,
                                uint8_t* __restrict__ blob0, uint8_t* __restrict__ blob1,
                                u64* __restrict__ psin, u64* __restrict__ psout) {
    int idx = blockIdx.x * 256 + threadIdx.x;
    if (idx < 2 * 100 * 32) {
        int lane = idx & 31;
        int set = (idx >> 5) % 100;
        int phase = (idx >> 5) / 100;
        uint8_t* blob = phase ? blob1 : blob0;

        const float* W; int NT, N, Kreal, sl, ob;
        if (set < 30)      { W = phase ? W20 : W10; NT = 10; N = 80; Kreal = 36; sl = set;      ob = BL1; }
        else if (set < 80) { W = phase ? W21 : W11; NT = 10; N = 80; Kreal = 80; sl = set - 30; ob = BL2; }
        else               { W = phase ? W22 : W12; NT = 4;  N = 32; Kreal = 80; sl = set - 80; ob = BL3; }

        int kt = sl / NT, nt = sl - kt * NT;
        int n = nt * 8 + (lane >> 2);
        int k0 = kt * 16 + 2 * (lane & 3);
        float v[4];
#pragma unroll
        for (int j = 0; j < 4; j++) {
            int k = k0 + (j >> 1) * 8 + (j & 1);
            v[j] = (k < Kreal) ? W[k * N + n] : 0.f;
        }
        uint32_t h0, l0, h1, l1;
        split_pack(v[0], v[1], h0, l0);
        split_pack(v[2], v[3], h1, l1);
        *(uint4*)(blob + ob + (size_t)sl * 512 + lane * 16) = make_uint4(h0, h1, l0, l1);
        return;
    }
    int j = idx - 2 * 100 * 32;
    if (j < N_PTS) {
        psin[j] = split_u64(gin[2 * j], gin[2 * j + 1]);
    } else if (j < N_PTS + M_PTS) {
        int m = j - N_PTS;
        psout[m] = split_u64(gout[2 * m], gout[2 * m + 1]);
    }
}

// ---------------- projection MLP (also writes split f) ----------------
__global__ void proj_kernel(const float* __restrict__ inp,
                            const float* __restrict__ W0, const float* __restrict__ b0,
                            const float* __restrict__ W1, const float* __restrict__ b1,
                            float* __restrict__ f0, u64* __restrict__ fsplit) {
    __shared__ float hs[4][64];
    int warp = threadIdx.x >> 5, lane = threadIdx.x & 31;
    int pv = blockIdx.x * 4 + warp;
    if (pv >= VARS * N_PTS) return;
    int v = pv / N_PTS, n = pv - v * N_PTS;
    const float* x = inp + n * (VARS * 8) + v * 8;
    float xr[8];
#pragma unroll
    for (int i = 0; i < 8; i++) xr[i] = x[i];
    float a0 = b0[lane], a1 = b0[lane + 32];
#pragma unroll
    for (int i = 0; i < 8; i++) {
        a0 = fmaf(xr[i], W0[i * 64 + lane], a0);
        a1 = fmaf(xr[i], W0[i * 64 + lane + 32], a1);
    }
    hs[warp][lane]      = gelu(a0);
    hs[warp][lane + 32] = gelu(a1);
    __syncwarp();
    float acc = b1[lane];
#pragma unroll
    for (int h = 0; h < 64; h++) acc = fmaf(hs[warp][h], W1[h * 32 + lane], acc);
    f0[(size_t)pv * 32 + lane] = acc;
    float accn = __shfl_down_sync(0xffffffffu, acc, 1);
    if (!(lane & 1))
        fsplit[(size_t)pv * 16 + (lane >> 1)] = split_u64(acc, accn);
}

// ---------------- HMMA edge MLP ----------------
// Block: 128 threads = 4 warps; each warp processes 2 tiles of 16 edges.
// A1 fragments loaded directly from pre-split node data (no xst staging).
#define TPB 128
#define SM_BS0   51200
#define SM_BS1   51520
#define SM_BS2   51840
#define SM_IDX   52224          // + warp*128: jn[16] + seg[16]
#define SMEM_BYTES 52736

template <int MODE>
__global__ void __launch_bounds__(TPB, 4)
edge_mma_kernel(const uint8_t* __restrict__ blob,
                const float* __restrict__ b0g, const float* __restrict__ b1g,
                const float* __restrict__ b2g,
                const u64* __restrict__ psin, const u64* __restrict__ psout,
                const u64* __restrict__ fsplit,
                const int* __restrict__ idxA, const int* __restrict__ idxB,
                float* __restrict__ outbuf, int E) {
    extern __shared__ __align__(16) uint8_t sm[];
    int tid = threadIdx.x;
    int warp = tid >> 5, lane = tid & 31;
    int g = lane >> 2;          // row group 0..7
    int t = lane & 3;           // thread-in-group
    int v = blockIdx.y;

    // stage blob + biases
    {
        const uint4* src = (const uint4*)blob;
        uint4* dst = (uint4*)sm;
        for (int i = tid; i < BLOB_BYTES / 16; i += TPB) dst[i] = src[i];
        float* bs0 = (float*)(sm + SM_BS0);
        float* bs1 = (float*)(sm + SM_BS1);
        float* bs2 = (float*)(sm + SM_BS2);
        if (tid < 80) { bs0[tid] = b0g[tid]; bs1[tid] = b1g[tid]; }
        if (tid < 32) bs2[tid] = b2g[tid];
    }
    __syncthreads();

    int* jn_sh  = (int*)(sm + SM_IDX + warp * 128);
    int* seg_sh = jn_sh + 16;
    const float* bs0 = (const float*)(sm + SM_BS0);
    const float* bs1 = (const float*)(sm + SM_BS1);
    const float* bs2 = (const float*)(sm + SM_BS2);

#pragma unroll 1
    for (int mt = 0; mt < 2; mt++) {
        int tileBase = blockIdx.x * 128 + warp * 32 + mt * 16;

        // ---- index stage: lanes 0..15 ----
        if (lane < 16) {
            int e = tileBase + lane;
            bool gv = e < E;
            int ee = gv ? e : 0;
            jn_sh[lane] = idxA[ee];
            seg_sh[lane] = gv ? ((MODE == 0) ? idxB[ee] : ee / K_LAST) : -1;
        }
        __syncwarp();

        // ---- A1 fragments loaded directly from split node data ----
        // cp(kt, t, rrHi) = 8*kt + t + 4*rrHi; cp0 = pos(jn), cp1 = pos(seg),
        // cp 2..17 = f pairs, cp >= 18 = zero.
        uint32_t a1h[3][4], a1l[3][4];
#pragma unroll
        for (int rs = 0; rs < 2; rs++) {
            int row = g + rs * 8;
            int jn = jn_sh[row];
            int sg = seg_sh[row];
            int sgc = sg < 0 ? 0 : sg;
            const u64* fb = fsplit + ((size_t)v * N_PTS + jn) * 16;
            u64 q00;
            if (t >= 2)      q00 = fb[t - 2];
            else if (t == 0) q00 = psin[jn];
            else             q00 = (MODE == 0) ? psin[sgc] : psout[sgc];
            u64 q01 = fb[2 + t];
            u64 q10 = fb[6 + t];
            u64 q11 = fb[10 + t];
            u64 q20 = (t < 2) ? fb[14 + t] : 0ULL;
            a1h[0][rs]     = (uint32_t)q00; a1l[0][rs]     = (uint32_t)(q00 >> 32);
            a1h[0][rs + 2] = (uint32_t)q01; a1l[0][rs + 2] = (uint32_t)(q01 >> 32);
            a1h[1][rs]     = (uint32_t)q10; a1l[1][rs]     = (uint32_t)(q10 >> 32);
            a1h[1][rs + 2] = (uint32_t)q11; a1l[1][rs + 2] = (uint32_t)(q11 >> 32);
            a1h[2][rs]     = (uint32_t)q20; a1l[2][rs]     = (uint32_t)(q20 >> 32);
            a1h[2][rs + 2] = 0u;            a1l[2][rs + 2] = 0u;
        }

        // ---- layer 1: K=48, N=80 (10 n-tiles) ----
        float d1[10][4];
#pragma unroll
        for (int nt = 0; nt < 10; nt++) {
            float* d = d1[nt];
            d[0] = 0.f; d[1] = 0.f; d[2] = 0.f; d[3] = 0.f;
#pragma unroll
            for (int kt = 0; kt < 3; kt++) {
                int set = kt * 10 + nt;
                uint4 q = *(const uint4*)(sm + BL1 + (size_t)set * 512 + lane * 16);
                mma16816(d, a1h[kt], q.x, q.y);
                mma16816(d, a1h[kt], q.z, q.w);
                mma16816(d, a1l[kt], q.x, q.y);
            }
        }

        // ---- epilogue 1: bias + gelu + split -> A2 fragments ----
        uint32_t a2h[5][4], a2l[5][4];
#pragma unroll
        for (int m = 0; m < 5; m++) {
            int j0 = 2 * m, j1 = 2 * m + 1;
            float bb0, bb1, bb2, bb3;
            unpk2(*(const u64*)(bs0 + 8 * j0 + 2 * t), bb0, bb1);
            unpk2(*(const u64*)(bs0 + 8 * j1 + 2 * t), bb2, bb3);
            float q0, q1;
            unpk2(gelu2(pk2(d1[j0][0] + bb0, d1[j0][1] + bb1)), q0, q1);
            split_pack(q0, q1, a2h[m][0], a2l[m][0]);
            unpk2(gelu2(pk2(d1[j0][2] + bb0, d1[j0][3] + bb1)), q0, q1);
            split_pack(q0, q1, a2h[m][1], a2l[m][1]);
            unpk2(gelu2(pk2(d1[j1][0] + bb2, d1[j1][1] + bb3)), q0, q1);
            split_pack(q0, q1, a2h[m][2], a2l[m][2]);
            unpk2(gelu2(pk2(d1[j1][2] + bb2, d1[j1][3] + bb3)), q0, q1);
            split_pack(q0, q1, a2h[m][3], a2l[m][3]);
        }

        // ---- layer 2: K=80, N=80 ----
        float d2[10][4];
#pragma unroll
        for (int nt = 0; nt < 10; nt++) {
            float* d = d2[nt];
            d[0] = 0.f; d[1] = 0.f; d[2] = 0.f; d[3] = 0.f;
#pragma unroll
            for (int kt = 0; kt < 5; kt++) {
                int set = kt * 10 + nt;
                uint4 q = *(const uint4*)(sm + BL2 + (size_t)set * 512 + lane * 16);
                mma16816(d, a2h[kt], q.x, q.y);
                mma16816(d, a2h[kt], q.z, q.w);
                mma16816(d, a2l[kt], q.x, q.y);
            }
        }

        // ---- epilogue 2 -> A3 fragments ----
        uint32_t a3h[5][4], a3l[5][4];
#pragma unroll
        for (int m = 0; m < 5; m++) {
            int j0 = 2 * m, j1 = 2 * m + 1;
            float bb0, bb1, bb2, bb3;
            unpk2(*(const u64*)(bs1 + 8 * j0 + 2 * t), bb0, bb1);
            unpk2(*(const u64*)(bs1 + 8 * j1 + 2 * t), bb2, bb3);
            float q0, q1;
            unpk2(gelu2(pk2(d2[j0][0] + bb0, d2[j0][1] + bb1)), q0, q1);
            split_pack(q0, q1, a3h[m][0], a3l[m][0]);
            unpk2(gelu2(pk2(d2[j0][2] + bb0, d2[j0][3] + bb1)), q0, q1);
            split_pack(q0, q1, a3h[m][1], a3l[m][1]);
            unpk2(gelu2(pk2(d2[j1][0] + bb2, d2[j1][1] + bb3)), q0, q1);
            split_pack(q0, q1, a3h[m][2], a3l[m][2]);
            unpk2(gelu2(pk2(d2[j1][2] + bb2, d2[j1][3] + bb3)), q0, q1);
            split_pack(q0, q1, a3h[m][3], a3l[m][3]);
        }

        // ---- layer 3: K=80, N=32 (4 n-tiles) ----
        float d3[4][4];
#pragma unroll
        for (int nt = 0; nt < 4; nt++) {
            float* d = d3[nt];
            d[0] = 0.f; d[1] = 0.f; d[2] = 0.f; d[3] = 0.f;
#pragma unroll
            for (int kt = 0; kt < 5; kt++) {
                int set = kt * 4 + nt;
                uint4 q = *(const uint4*)(sm + BL3 + (size_t)set * 512 + lane * 16);
                mma16816(d, a3h[kt], q.x, q.y);
                mma16816(d, a3h[kt], q.z, q.w);
                mma16816(d, a3l[kt], q.x, q.y);
            }
        }

        // ---- epilogue 3: bias + scatter (rows g and g+8) ----
        {
            int sg0 = seg_sh[g], sg1 = seg_sh[g + 8];
            float scale = (MODE == 0) ? 1.0f : 0.1f;
            float* dst0 = nullptr; float* dst1 = nullptr;
            if (MODE == 0) {
                if (sg0 >= 0) dst0 = outbuf + ((size_t)v * N_PTS + sg0) * 32;
                if (sg1 >= 0) dst1 = outbuf + ((size_t)v * N_PTS + sg1) * 32;
            } else {
                if (sg0 >= 0) dst0 = outbuf + (size_t)sg0 * (VARS * 32) + v * 32;
                if (sg1 >= 0) dst1 = outbuf + (size_t)sg1 * (VARS * 32) + v * 32;
            }
#pragma unroll
            for (int nt = 0; nt < 4; nt++) {
                float bb0, bb1;
                unpk2(*(const u64*)(bs2 + 8 * nt + 2 * t), bb0, bb1);
                int c0 = 8 * nt + 2 * t;
                if (dst0) {
                    atomicAdd(dst0 + c0,     (d3[nt][0] + bb0) * scale);
                    atomicAdd(dst0 + c0 + 1, (d3[nt][1] + bb1) * scale);
                }
                if (dst1) {
                    atomicAdd(dst1 + c0,     (d3[nt][2] + bb0) * scale);
                    atomicAdd(dst1 + c0 + 1, (d3[nt][3] + bb1) * scale);
                }
            }
        }
        __syncwarp();
    }
}

// f1 = segment_sum * inv_count + f0 (in place), also refresh fsplit
__global__ void f1_kernel(float* __restrict__ f0, const float* __restrict__ acc,
                          const int* __restrict__ counts, u64* __restrict__ fsplit) {
    int p = blockIdx.x * 256 + threadIdx.x;
    if (p >= VARS * N_PTS * 16) return;
    int n = (p >> 4) % N_PTS;
    int c = counts[n];
    float inv = 1.0f / (float)(c > 1 ? c : 1);
    float a0, a1, fa, fb;
    unpk2(((const u64*)acc)[p], a0, a1);
    unpk2(((const u64*)f0)[p], fa, fb);
    float r0 = fmaf(a0, inv, fa);
    float r1 = fmaf(a1, inv, fb);
    ((u64*)f0)[p] = pk2(r0, r1);
    fsplit[p] = split_u64(r0, r1);
}

extern "C" void kernel_launch(void* const* d_in, const int* in_sizes, int n_in,
                              void* d_out, int out_size) {
    const float* inp   = (const float*)d_in[0];
    const float* gin   = (const float*)d_in[1];
    const float* gout  = (const float*)d_in[2];
    const float* pW0   = (const float*)d_in[3];
    const float* pb0   = (const float*)d_in[4];
    const float* pW1   = (const float*)d_in[5];
    const float* pb1   = (const float*)d_in[6];
    const float* i0W0  = (const float*)d_in[7];
    const float* i0b0  = (const float*)d_in[8];
    const float* i0W1  = (const float*)d_in[9];
    const float* i0b1  = (const float*)d_in[10];
    const float* i0W2  = (const float*)d_in[11];
    const float* i0b2  = (const float*)d_in[12];
    const float* i1W0  = (const float*)d_in[13];
    const float* i1b0  = (const float*)d_in[14];
    const float* i1W1  = (const float*)d_in[15];
    const float* i1b1  = (const float*)d_in[16];
    const float* i1W2  = (const float*)d_in[17];
    const float* i1b2  = (const float*)d_in[18];
    const int* nbr_index  = (const int*)d_in[19];
    const int* nbr_seg    = (const int*)d_in[20];
    const int* nbr_counts = (const int*)d_in[21];
    const int* nbr_last   = (const int*)d_in[22];
    int E = in_sizes[19];

    float *f0, *acc;
    u64 *fsplit, *psin, *psout;
    uint8_t* blob;
    cudaGetSymbolAddress((void**)&f0,     g_f0);
    cudaGetSymbolAddress((void**)&acc,    g_acc);
    cudaGetSymbolAddress((void**)&fsplit, g_fsplit);
    cudaGetSymbolAddress((void**)&psin,   g_psin);
    cudaGetSymbolAddress((void**)&psout,  g_psout);
    cudaGetSymbolAddress((void**)&blob,   g_blob);
    uint8_t* blob0 = blob;
    uint8_t* blob1 = blob + BLOB_BYTES;

    cudaMemsetAsync(acc, 0, sizeof(float) * VARS * N_PTS * 32);
    cudaMemsetAsync(d_out, 0, sizeof(float) * (size_t)out_size);

    // fused prep: weight blobs (both phases) + split positions
    const int PREP_T = 2 * 100 * 32 + N_PTS + M_PTS;
    prep_all_kernel<<<(PREP_T + 255) / 256, 256>>>(i0W0, i0W1, i0W2,
                                                   i1W0, i1W1, i1W2,
                                                   gin, gout, blob0, blob1, psin, psout);

    proj_kernel<<<(VARS * N_PTS + 3) / 4, 128>>>(inp, pW0, pb0, pW1, pb1, f0, fsplit);

    cudaFuncSetAttribute(edge_mma_kernel<0>, cudaFuncAttributeMaxDynamicSharedMemorySize, SMEM_BYTES);
    cudaFuncSetAttribute(edge_mma_kernel<1>, cudaFuncAttributeMaxDynamicSharedMemorySize, SMEM_BYTES);

    dim3 g1((unsigned)((E + 127) / 128), VARS);
    edge_mma_kernel<0><<<g1, TPB, SMEM_BYTES>>>(blob0, i0b0, i0b1, i0b2,
                                                psin, psout, fsplit,
                                                nbr_index, nbr_seg, acc, E);

    f1_kernel<<<(VARS * N_PTS * 16 + 255) / 256, 256>>>(f0, acc, nbr_counts, fsplit);

    int E2 = M_PTS * K_LAST;
    dim3 g2((unsigned)((E2 + 127) / 128), VARS);
    edge_mma_kernel<1><<<g2, TPB, SMEM_BYTES>>>(blob1, i1b0, i1b1, i1b2,
                                                psin, psout, fsplit,
                                                nbr_last, nullptr, (float*)d_out, E2);
}

// round 16
// speedup vs baseline: 1.6781x; 1.0072x over previous
#include <cuda_runtime.h>
#include <cuda_bf16.h>
#include <math.h>
#include <stdint.h>

#define N_PTS 8192
#define M_PTS 2048
#define K_LAST 10
#define VARS 3

typedef unsigned long long u64;

// ---------------- packed f32x2 helpers ----------------
__device__ __forceinline__ u64 pk2(float lo, float hi) {
    u64 r; asm("mov.b64 %0,{%1,%2};" : "=l"(r) : "f"(lo), "f"(hi)); return r;
}
__device__ __forceinline__ void unpk2(u64 v, float& lo, float& hi) {
    asm("mov.b64 {%0,%1},%2;" : "=f"(lo), "=f"(hi) : "l"(v));
}
__device__ __forceinline__ u64 f2fma(u64 a, u64 b, u64 c) {
    u64 d; asm("fma.rn.f32x2 %0,%1,%2,%3;" : "=l"(d) : "l"(a), "l"(b), "l"(c)); return d;
}
__device__ __forceinline__ u64 f2mul(u64 a, u64 b) {
    u64 d; asm("mul.rn.f32x2 %0,%1,%2;" : "=l"(d) : "l"(a), "l"(b)); return d;
}
__device__ __forceinline__ u64 dup2(float x) { return pk2(x, x); }

__device__ __forceinline__ float gelu(float x) {
    return 0.5f * x * (1.0f + erff(x * 0.70710678118654752f));
}

// packed GELU (A&S 7.1.26 erf, abs err <= 1.5e-7)
__device__ __forceinline__ u64 gelu2(u64 x) {
    u64 ax = x & 0x7FFFFFFF7FFFFFFFULL;
    u64 z  = f2mul(ax, dup2(0.70710678118654752f));
    u64 den = f2fma(z, dup2(0.3275911f), dup2(1.0f));
    float dl, dh, rl, rh;
    unpk2(den, dl, dh);
    asm("rcp.approx.f32 %0,%1;" : "=f"(rl) : "f"(dl));
    asm("rcp.approx.f32 %0,%1;" : "=f"(rh) : "f"(dh));
    u64 t = pk2(rl, rh);
    u64 z2 = f2mul(z, z);
    u64 m  = f2mul(z2, dup2(-1.4426950408889634f));
    float ml, mh, el, eh;
    unpk2(m, ml, mh);
    asm("ex2.approx.f32 %0,%1;" : "=f"(el) : "f"(ml));
    asm("ex2.approx.f32 %0,%1;" : "=f"(eh) : "f"(mh));
    u64 e = pk2(el, eh);
    u64 p = f2fma(t, dup2(1.061405429f), dup2(-1.453152027f));
    p = f2fma(p, t, dup2(1.421413741f));
    p = f2fma(p, t, dup2(-0.284496736f));
    p = f2fma(p, t, dup2(0.254829592f));
    p = f2mul(p, t);
    u64 np = p ^ 0x8000000080000000ULL;
    u64 u  = f2fma(np, e, dup2(1.0f));
    u64 E  = u | (x & 0x8000000080000000ULL);
    u64 h  = f2fma(E, dup2(0.5f), dup2(0.5f));
    return f2mul(x, h);
}

// pack two floats to bf16x2 (a -> low 16 bits, b -> high)
__device__ __forceinline__ uint32_t pack_bf16(float a, float b) {
    uint32_t r; asm("cvt.rn.bf16x2.f32 %0, %1, %2;" : "=r"(r) : "f"(b), "f"(a));
    return r;
}
// split f32 pair into (hi bf16x2, lo bf16x2)
__device__ __forceinline__ void split_pack(float f0, float f1, uint32_t& hi, uint32_t& lo) {
    hi = pack_bf16(f0, f1);
    float h0 = __uint_as_float(hi << 16);
    float h1 = __uint_as_float(hi & 0xFFFF0000u);
    lo = pack_bf16(f0 - h0, f1 - h1);
}
__device__ __forceinline__ u64 split_u64(float f0, float f1) {
    uint32_t h, l; split_pack(f0, f1, h, l);
    return (u64)h | ((u64)l << 32);
}

// m16n8k16 bf16 MMA, D (f32) accumulate in place
__device__ __forceinline__ void mma16816(float* d, const uint32_t* a, uint32_t b0, uint32_t b1) {
    asm volatile(
        "mma.sync.aligned.m16n8k16.row.col.f32.bf16.bf16.f32 "
        "{%0,%1,%2,%3}, {%4,%5,%6,%7}, {%8,%9}, {%0,%1,%2,%3};"
        : "+f"(d[0]), "+f"(d[1]), "+f"(d[2]), "+f"(d[3])
        : "r"(a[0]), "r"(a[1]), "r"(a[2]), "r"(a[3]), "r"(b0), "r"(b1));
}

// ---------------- scratch ----------------
__device__ float g_f0[VARS * N_PTS * 32];
__device__ float g_acc[VARS * N_PTS * 32];
__device__ u64   g_fsplit[VARS * N_PTS * 16];  // {hi,lo} bf16x2 per col-pair
__device__ u64   g_psin[N_PTS];                // split input-grid positions
__device__ u64   g_psout[M_PTS];               // split output-grid positions
__device__ uint8_t g_blob[2][51200];
// interleaved blob: per set 512B, lane entry = uint4 {bh0, bh1, bl0, bl1}
#define BL1 0        // 30 sets * 512
#define BL2 15360    // 50 sets * 512
#define BL3 40960    // 20 sets * 512
#define BLOB_BYTES 51200

// ---------------- fused weight prep + split positions ----------------
__global__ void prep_all_kernel(const float* __restrict__ W10, const float* __restrict__ W11,
                                const float* __restrict__ W12,
                                const float* __restrict__ W20, const float* __restrict__ W21,
                                const float* __restrict__ W22,
                                const float* __restrict__ gin, const float* __restrict__ gout,
                                uint8_t* __restrict__ blob0, uint8_t* __restrict__ blob1,
                                u64* __restrict__ psin, u64* __restrict__ psout) {
    int idx = blockIdx.x * 256 + threadIdx.x;
    if (idx < 2 * 100 * 32) {
        int lane = idx & 31;
        int set = (idx >> 5) % 100;
        int phase = (idx >> 5) / 100;
        uint8_t* blob = phase ? blob1 : blob0;

        const float* W; int NT, N, Kreal, sl, ob;
        if (set < 30)      { W = phase ? W20 : W10; NT = 10; N = 80; Kreal = 36; sl = set;      ob = BL1; }
        else if (set < 80) { W = phase ? W21 : W11; NT = 10; N = 80; Kreal = 80; sl = set - 30; ob = BL2; }
        else               { W = phase ? W22 : W12; NT = 4;  N = 32; Kreal = 80; sl = set - 80; ob = BL3; }

        int kt = sl / NT, nt = sl - kt * NT;
        int n = nt * 8 + (lane >> 2);
        int k0 = kt * 16 + 2 * (lane & 3);
        float v[4];
#pragma unroll
        for (int j = 0; j < 4; j++) {
            int k = k0 + (j >> 1) * 8 + (j & 1);
            v[j] = (k < Kreal) ? W[k * N + n] : 0.f;
        }
        uint32_t h0, l0, h1, l1;
        split_pack(v[0], v[1], h0, l0);
        split_pack(v[2], v[3], h1, l1);
        *(uint4*)(blob + ob + (size_t)sl * 512 + lane * 16) = make_uint4(h0, h1, l0, l1);
        return;
    }
    int j = idx - 2 * 100 * 32;
    if (j < N_PTS) {
        psin[j] = split_u64(gin[2 * j], gin[2 * j + 1]);
    } else if (j < N_PTS + M_PTS) {
        int m = j - N_PTS;
        psout[m] = split_u64(gout[2 * m], gout[2 * m + 1]);
    }
}

// ---------------- projection MLP (also writes split f) ----------------
__global__ void proj_kernel(const float* __restrict__ inp,
                            const float* __restrict__ W0, const float* __restrict__ b0,
                            const float* __restrict__ W1, const float* __restrict__ b1,
                            float* __restrict__ f0, u64* __restrict__ fsplit) {
    __shared__ float hs[4][64];
    int warp = threadIdx.x >> 5, lane = threadIdx.x & 31;
    int pv = blockIdx.x * 4 + warp;
    if (pv >= VARS * N_PTS) return;
    int v = pv / N_PTS, n = pv - v * N_PTS;
    const float* x = inp + n * (VARS * 8) + v * 8;
    float xr[8];
#pragma unroll
    for (int i = 0; i < 8; i++) xr[i] = x[i];
    float a0 = b0[lane], a1 = b0[lane + 32];
#pragma unroll
    for (int i = 0; i < 8; i++) {
        a0 = fmaf(xr[i], W0[i * 64 + lane], a0);
        a1 = fmaf(xr[i], W0[i * 64 + lane + 32], a1);
    }
    hs[warp][lane]      = gelu(a0);
    hs[warp][lane + 32] = gelu(a1);
    __syncwarp();
    float acc = b1[lane];
#pragma unroll
    for (int h = 0; h < 64; h++) acc = fmaf(hs[warp][h], W1[h * 32 + lane], acc);
    f0[(size_t)pv * 32 + lane] = acc;
    float accn = __shfl_down_sync(0xffffffffu, acc, 1);
    if (!(lane & 1))
        fsplit[(size_t)pv * 16 + (lane >> 1)] = split_u64(acc, accn);
}

// ---------------- HMMA edge MLP ----------------
// Block: 128 threads = 4 warps; each warp processes 2 tiles of 16 edges.
// ZERO shared memory: weights/biases via __ldg (L1D-resident across CTAs),
// edge indices shared via shuffles, biases folded into MMA accumulator init.
#define TPB 128

template <int MODE>
__global__ void __launch_bounds__(TPB, 4)
edge_mma_kernel(const uint8_t* __restrict__ blob,
                const float* __restrict__ b0g, const float* __restrict__ b1g,
                const float* __restrict__ b2g,
                const u64* __restrict__ psin, const u64* __restrict__ psout,
                const u64* __restrict__ fsplit,
                const int* __restrict__ idxA, const int* __restrict__ idxB,
                float* __restrict__ outbuf, int E) {
    int tid = threadIdx.x;
    int warp = tid >> 5, lane = tid & 31;
    int g = lane >> 2;          // row group 0..7
    int t = lane & 3;           // thread-in-group
    int v = blockIdx.y;

#pragma unroll 1
    for (int mt = 0; mt < 2; mt++) {
        int tileBase = blockIdx.x * 128 + warp * 32 + mt * 16;

        // ---- indices: lanes 0..15 load, all lanes shuffle their rows ----
        int jnv = 0, sgv = -1;
        {
            int e = tileBase + (lane & 15);
            bool gv = e < E;
            int ee = gv ? e : 0;
            if (lane < 16) {
                jnv = __ldg(idxA + ee);
                sgv = gv ? ((MODE == 0) ? __ldg(idxB + ee) : ee / K_LAST) : -1;
            }
        }
        int jn0 = __shfl_sync(0xffffffffu, jnv, g);
        int sg0 = __shfl_sync(0xffffffffu, sgv, g);
        int jn1 = __shfl_sync(0xffffffffu, jnv, g + 8);
        int sg1 = __shfl_sync(0xffffffffu, sgv, g + 8);

        // ---- A1 fragments from pre-split node data ----
        uint32_t a1h[3][4], a1l[3][4];
#pragma unroll
        for (int rs = 0; rs < 2; rs++) {
            int jn = rs ? jn1 : jn0;
            int sg = rs ? sg1 : sg0;
            int sgc = sg < 0 ? 0 : sg;
            const u64* fb = fsplit + ((size_t)v * N_PTS + jn) * 16;
            u64 q00;
            if (t >= 2)      q00 = __ldg(fb + (t - 2));
            else if (t == 0) q00 = __ldg(psin + jn);
            else             q00 = (MODE == 0) ? __ldg(psin + sgc) : __ldg(psout + sgc);
            u64 q01 = __ldg(fb + 2 + t);
            u64 q10 = __ldg(fb + 6 + t);
            u64 q11 = __ldg(fb + 10 + t);
            u64 q20 = (t < 2) ? __ldg(fb + 14 + t) : 0ULL;
            a1h[0][rs]     = (uint32_t)q00; a1l[0][rs]     = (uint32_t)(q00 >> 32);
            a1h[0][rs + 2] = (uint32_t)q01; a1l[0][rs + 2] = (uint32_t)(q01 >> 32);
            a1h[1][rs]     = (uint32_t)q10; a1l[1][rs]     = (uint32_t)(q10 >> 32);
            a1h[1][rs + 2] = (uint32_t)q11; a1l[1][rs + 2] = (uint32_t)(q11 >> 32);
            a1h[2][rs]     = (uint32_t)q20; a1l[2][rs]     = (uint32_t)(q20 >> 32);
            a1h[2][rs + 2] = 0u;            a1l[2][rs + 2] = 0u;
        }

        // ---- layer 1: K=48, N=80 (10 n-tiles), bias folded into init ----
        float d1[10][4];
#pragma unroll
        for (int nt = 0; nt < 10; nt++) {
            float* d = d1[nt];
            float b0f, b1f;
            unpk2(__ldg((const u64*)(b0g + 8 * nt + 2 * t)), b0f, b1f);
            d[0] = b0f; d[1] = b1f; d[2] = b0f; d[3] = b1f;
#pragma unroll
            for (int kt = 0; kt < 3; kt++) {
                int set = kt * 10 + nt;
                uint4 q = __ldg((const uint4*)(blob + BL1 + (size_t)set * 512 + lane * 16));
                mma16816(d, a1h[kt], q.x, q.y);
                mma16816(d, a1h[kt], q.z, q.w);
                mma16816(d, a1l[kt], q.x, q.y);
            }
        }

        // ---- epilogue 1: gelu + split -> A2 fragments ----
        uint32_t a2h[5][4], a2l[5][4];
#pragma unroll
        for (int m = 0; m < 5; m++) {
            int j0 = 2 * m, j1 = 2 * m + 1;
            float q0, q1;
            unpk2(gelu2(pk2(d1[j0][0], d1[j0][1])), q0, q1);
            split_pack(q0, q1, a2h[m][0], a2l[m][0]);
            unpk2(gelu2(pk2(d1[j0][2], d1[j0][3])), q0, q1);
            split_pack(q0, q1, a2h[m][1], a2l[m][1]);
            unpk2(gelu2(pk2(d1[j1][0], d1[j1][1])), q0, q1);
            split_pack(q0, q1, a2h[m][2], a2l[m][2]);
            unpk2(gelu2(pk2(d1[j1][2], d1[j1][3])), q0, q1);
            split_pack(q0, q1, a2h[m][3], a2l[m][3]);
        }

        // ---- layer 2: K=80, N=80 ----
        float d2[10][4];
#pragma unroll
        for (int nt = 0; nt < 10; nt++) {
            float* d = d2[nt];
            float b0f, b1f;
            unpk2(__ldg((const u64*)(b1g + 8 * nt + 2 * t)), b0f, b1f);
            d[0] = b0f; d[1] = b1f; d[2] = b0f; d[3] = b1f;
#pragma unroll
            for (int kt = 0; kt < 5; kt++) {
                int set = kt * 10 + nt;
                uint4 q = __ldg((const uint4*)(blob + BL2 + (size_t)set * 512 + lane * 16));
                mma16816(d, a2h[kt], q.x, q.y);
                mma16816(d, a2h[kt], q.z, q.w);
                mma16816(d, a2l[kt], q.x, q.y);
            }
        }

        // ---- epilogue 2 -> A3 fragments ----
        uint32_t a3h[5][4], a3l[5][4];
#pragma unroll
        for (int m = 0; m < 5; m++) {
            int j0 = 2 * m, j1 = 2 * m + 1;
            float q0, q1;
            unpk2(gelu2(pk2(d2[j0][0], d2[j0][1])), q0, q1);
            split_pack(q0, q1, a3h[m][0], a3l[m][0]);
            unpk2(gelu2(pk2(d2[j0][2], d2[j0][3])), q0, q1);
            split_pack(q0, q1, a3h[m][1], a3l[m][1]);
            unpk2(gelu2(pk2(d2[j1][0], d2[j1][1])), q0, q1);
            split_pack(q0, q1, a3h[m][2], a3l[m][2]);
            unpk2(gelu2(pk2(d2[j1][2], d2[j1][3])), q0, q1);
            split_pack(q0, q1, a3h[m][3], a3l[m][3]);
        }

        // ---- layer 3: K=80, N=32 (4 n-tiles) + scatter ----
        float scale = (MODE == 0) ? 1.0f : 0.1f;
        float* dst0 = nullptr; float* dst1 = nullptr;
        if (MODE == 0) {
            if (sg0 >= 0) dst0 = outbuf + ((size_t)v * N_PTS + sg0) * 32;
            if (sg1 >= 0) dst1 = outbuf + ((size_t)v * N_PTS + sg1) * 32;
        } else {
            if (sg0 >= 0) dst0 = outbuf + (size_t)sg0 * (VARS * 32) + v * 32;
            if (sg1 >= 0) dst1 = outbuf + (size_t)sg1 * (VARS * 32) + v * 32;
        }
#pragma unroll
        for (int nt = 0; nt < 4; nt++) {
            float d[4];
            float b0f, b1f;
            unpk2(__ldg((const u64*)(b2g + 8 * nt + 2 * t)), b0f, b1f);
            d[0] = b0f; d[1] = b1f; d[2] = b0f; d[3] = b1f;
#pragma unroll
            for (int kt = 0; kt < 5; kt++) {
                int set = kt * 4 + nt;
                uint4 q = __ldg((const uint4*)(blob + BL3 + (size_t)set * 512 + lane * 16));
                mma16816(d, a3h[kt], q.x, q.y);
                mma16816(d, a3h[kt], q.z, q.w);
                mma16816(d, a3l[kt], q.x, q.y);
            }
            int c0 = 8 * nt + 2 * t;
            if (dst0) {
                atomicAdd(dst0 + c0,     d[0] * scale);
                atomicAdd(dst0 + c0 + 1, d[1] * scale);
            }
            if (dst1) {
                atomicAdd(dst1 + c0,     d[2] * scale);
                atomicAdd(dst1 + c0 + 1, d[3] * scale);
            }
        }
    }
}

// f1 = segment_sum * inv_count + f0 (in place), also refresh fsplit
__global__ void f1_kernel(float* __restrict__ f0, const float* __restrict__ acc,
                          const int* __restrict__ counts, u64* __restrict__ fsplit) {
    int p = blockIdx.x * 256 + threadIdx.x;
    if (p >= VARS * N_PTS * 16) return;
    int n = (p >> 4) % N_PTS;
    int c = counts[n];
    float inv = 1.0f / (float)(c > 1 ? c : 1);
    float a0, a1, fa, fb;
    unpk2(((const u64*)acc)[p], a0, a1);
    unpk2(((const u64*)f0)[p], fa, fb);
    float r0 = fmaf(a0, inv, fa);
    float r1 = fmaf(a1, inv, fb);
    ((u64*)f0)[p] = pk2(r0, r1);
    fsplit[p] = split_u64(r0, r1);
}

extern "C" void kernel_launch(void* const* d_in, const int* in_sizes, int n_in,
                              void* d_out, int out_size) {
    const float* inp   = (const float*)d_in[0];
    const float* gin   = (const float*)d_in[1];
    const float* gout  = (const float*)d_in[2];
    const float* pW0   = (const float*)d_in[3];
    const float* pb0   = (const float*)d_in[4];
    const float* pW1   = (const float*)d_in[5];
    const float* pb1   = (const float*)d_in[6];
    const float* i0W0  = (const float*)d_in[7];
    const float* i0b0  = (const float*)d_in[8];
    const float* i0W1  = (const float*)d_in[9];
    const float* i0b1  = (const float*)d_in[10];
    const float* i0W2  = (const float*)d_in[11];
    const float* i0b2  = (const float*)d_in[12];
    const float* i1W0  = (const float*)d_in[13];
    const float* i1b0  = (const float*)d_in[14];
    const float* i1W1  = (const float*)d_in[15];
    const float* i1b1  = (const float*)d_in[16];
    const float* i1W2  = (const float*)d_in[17];
    const float* i1b2  = (const float*)d_in[18];
    const int* nbr_index  = (const int*)d_in[19];
    const int* nbr_seg    = (const int*)d_in[20];
    const int* nbr_counts = (const int*)d_in[21];
    const int* nbr_last   = (const int*)d_in[22];
    int E = in_sizes[19];

    float *f0, *acc;
    u64 *fsplit, *psin, *psout;
    uint8_t* blob;
    cudaGetSymbolAddress((void**)&f0,     g_f0);
    cudaGetSymbolAddress((void**)&acc,    g_acc);
    cudaGetSymbolAddress((void**)&fsplit, g_fsplit);
    cudaGetSymbolAddress((void**)&psin,   g_psin);
    cudaGetSymbolAddress((void**)&psout,  g_psout);
    cudaGetSymbolAddress((void**)&blob,   g_blob);
    uint8_t* blob0 = blob;
    uint8_t* blob1 = blob + BLOB_BYTES;

    cudaMemsetAsync(acc, 0, sizeof(float) * VARS * N_PTS * 32);
    cudaMemsetAsync(d_out, 0, sizeof(float) * (size_t)out_size);

    // fused prep: weight blobs (both phases) + split positions
    const int PREP_T = 2 * 100 * 32 + N_PTS + M_PTS;
    prep_all_kernel<<<(PREP_T + 255) / 256, 256>>>(i0W0, i0W1, i0W2,
                                                   i1W0, i1W1, i1W2,
                                                   gin, gout, blob0, blob1, psin, psout);

    proj_kernel<<<(VARS * N_PTS + 3) / 4, 128>>>(inp, pW0, pb0, pW1, pb1, f0, fsplit);

    dim3 g1((unsigned)((E + 127) / 128), VARS);
    edge_mma_kernel<0><<<g1, TPB>>>(blob0, i0b0, i0b1, i0b2,
                                    psin, psout, fsplit,
                                    nbr_index, nbr_seg, acc, E);

    f1_kernel<<<(VARS * N_PTS * 16 + 255) / 256, 256>>>(f0, acc, nbr_counts, fsplit);

    int E2 = M_PTS * K_LAST;
    dim3 g2((unsigned)((E2 + 127) / 128), VARS);
    edge_mma_kernel<1><<<g2, TPB>>>(blob1, i1b0, i1b1, i1b2,
                                    psin, psout, fsplit,
                                    nbr_last, nullptr, (float*)d_out, E2);
}

// round 17
// speedup vs baseline: 1.6831x; 1.0029x over previous
#include <cuda_runtime.h>
#include <cuda_bf16.h>
#include <math.h>
#include <stdint.h>

#define N_PTS 8192
#define M_PTS 2048
#define K_LAST 10
#define VARS 3

typedef unsigned long long u64;

// ---------------- packed f32x2 helpers ----------------
__device__ __forceinline__ u64 pk2(float lo, float hi) {
    u64 r; asm("mov.b64 %0,{%1,%2};" : "=l"(r) : "f"(lo), "f"(hi)); return r;
}
__device__ __forceinline__ void unpk2(u64 v, float& lo, float& hi) {
    asm("mov.b64 {%0,%1},%2;" : "=f"(lo), "=f"(hi) : "l"(v));
}
__device__ __forceinline__ u64 f2fma(u64 a, u64 b, u64 c) {
    u64 d; asm("fma.rn.f32x2 %0,%1,%2,%3;" : "=l"(d) : "l"(a), "l"(b), "l"(c)); return d;
}
__device__ __forceinline__ u64 f2mul(u64 a, u64 b) {
    u64 d; asm("mul.rn.f32x2 %0,%1,%2;" : "=l"(d) : "l"(a), "l"(b)); return d;
}
__device__ __forceinline__ u64 dup2(float x) { return pk2(x, x); }

__device__ __forceinline__ float gelu(float x) {
    return 0.5f * x * (1.0f + erff(x * 0.70710678118654752f));
}

// packed GELU (A&S 7.1.26 erf, abs err <= 1.5e-7)
__device__ __forceinline__ u64 gelu2(u64 x) {
    u64 ax = x & 0x7FFFFFFF7FFFFFFFULL;
    u64 z  = f2mul(ax, dup2(0.70710678118654752f));
    u64 den = f2fma(z, dup2(0.3275911f), dup2(1.0f));
    float dl, dh, rl, rh;
    unpk2(den, dl, dh);
    asm("rcp.approx.f32 %0,%1;" : "=f"(rl) : "f"(dl));
    asm("rcp.approx.f32 %0,%1;" : "=f"(rh) : "f"(dh));
    u64 t = pk2(rl, rh);
    u64 z2 = f2mul(z, z);
    u64 m  = f2mul(z2, dup2(-1.4426950408889634f));
    float ml, mh, el, eh;
    unpk2(m, ml, mh);
    asm("ex2.approx.f32 %0,%1;" : "=f"(el) : "f"(ml));
    asm("ex2.approx.f32 %0,%1;" : "=f"(eh) : "f"(mh));
    u64 e = pk2(el, eh);
    u64 p = f2fma(t, dup2(1.061405429f), dup2(-1.453152027f));
    p = f2fma(p, t, dup2(1.421413741f));
    p = f2fma(p, t, dup2(-0.284496736f));
    p = f2fma(p, t, dup2(0.254829592f));
    p = f2mul(p, t);
    u64 np = p ^ 0x8000000080000000ULL;
    u64 u  = f2fma(np, e, dup2(1.0f));
    u64 E  = u | (x & 0x8000000080000000ULL);
    u64 h  = f2fma(E, dup2(0.5f), dup2(0.5f));
    return f2mul(x, h);
}

// pack two floats to bf16x2 (a -> low 16 bits, b -> high)
__device__ __forceinline__ uint32_t pack_bf16(float a, float b) {
    uint32_t r; asm("cvt.rn.bf16x2.f32 %0, %1, %2;" : "=r"(r) : "f"(b), "f"(a));
    return r;
}
// split f32 pair into (hi bf16x2, lo bf16x2)
__device__ __forceinline__ void split_pack(float f0, float f1, uint32_t& hi, uint32_t& lo) {
    hi = pack_bf16(f0, f1);
    float h0 = __uint_as_float(hi << 16);
    float h1 = __uint_as_float(hi & 0xFFFF0000u);
    lo = pack_bf16(f0 - h0, f1 - h1);
}
__device__ __forceinline__ u64 split_u64(float f0, float f1) {
    uint32_t h, l; split_pack(f0, f1, h, l);
    return (u64)h | ((u64)l << 32);
}

// m16n8k16 bf16 MMA, D (f32) accumulate in place
__device__ __forceinline__ void mma16816(float* d, const uint32_t* a, uint32_t b0, uint32_t b1) {
    asm volatile(
        "mma.sync.aligned.m16n8k16.row.col.f32.bf16.bf16.f32 "
        "{%0,%1,%2,%3}, {%4,%5,%6,%7}, {%8,%9}, {%0,%1,%2,%3};"
        : "+f"(d[0]), "+f"(d[1]), "+f"(d[2]), "+f"(d[3])
        : "r"(a[0]), "r"(a[1]), "r"(a[2]), "r"(a[3]), "r"(b0), "r"(b1));
}

// vectored global reduction: one instruction commits 2 adjacent floats
__device__ __forceinline__ void red2(float* p, float a, float b) {
    asm volatile("red.global.add.v2.f32 [%0], {%1, %2};"
                 :: "l"(p), "f"(a), "f"(b) : "memory");
}

// ---------------- scratch ----------------
__device__ float g_f0[VARS * N_PTS * 32];
__device__ float g_acc[VARS * N_PTS * 32];
__device__ u64   g_fsplit[VARS * N_PTS * 16];  // {hi,lo} bf16x2 per col-pair
__device__ u64   g_psin[N_PTS];                // split input-grid positions
__device__ u64   g_psout[M_PTS];               // split output-grid positions
__device__ uint8_t g_blob[2][51200];
// interleaved blob: per set 512B, lane entry = uint4 {bh0, bh1, bl0, bl1}
#define BL1 0        // 30 sets * 512
#define BL2 15360    // 50 sets * 512
#define BL3 40960    // 20 sets * 512
#define BLOB_BYTES 51200

// ---------------- fused weight prep + split positions ----------------
__global__ void prep_all_kernel(const float* __restrict__ W10, const float* __restrict__ W11,
                                const float* __restrict__ W12,
                                const float* __restrict__ W20, const float* __restrict__ W21,
                                const float* __restrict__ W22,
                                const float* __restrict__ gin, const float* __restrict__ gout,
                                uint8_t* __restrict__ blob0, uint8_t* __restrict__ blob1,
                                u64* __restrict__ psin, u64* __restrict__ psout) {
    int idx = blockIdx.x * 256 + threadIdx.x;
    if (idx < 2 * 100 * 32) {
        int lane = idx & 31;
        int set = (idx >> 5) % 100;
        int phase = (idx >> 5) / 100;
        uint8_t* blob = phase ? blob1 : blob0;

        const float* W; int NT, N, Kreal, sl, ob;
        if (set < 30)      { W = phase ? W20 : W10; NT = 10; N = 80; Kreal = 36; sl = set;      ob = BL1; }
        else if (set < 80) { W = phase ? W21 : W11; NT = 10; N = 80; Kreal = 80; sl = set - 30; ob = BL2; }
        else               { W = phase ? W22 : W12; NT = 4;  N = 32; Kreal = 80; sl = set - 80; ob = BL3; }

        int kt = sl / NT, nt = sl - kt * NT;
        int n = nt * 8 + (lane >> 2);
        int k0 = kt * 16 + 2 * (lane & 3);
        float v[4];
#pragma unroll
        for (int j = 0; j < 4; j++) {
            int k = k0 + (j >> 1) * 8 + (j & 1);
            v[j] = (k < Kreal) ? W[k * N + n] : 0.f;
        }
        uint32_t h0, l0, h1, l1;
        split_pack(v[0], v[1], h0, l0);
        split_pack(v[2], v[3], h1, l1);
        *(uint4*)(blob + ob + (size_t)sl * 512 + lane * 16) = make_uint4(h0, h1, l0, l1);
        return;
    }
    int j = idx - 2 * 100 * 32;
    if (j < N_PTS) {
        psin[j] = split_u64(gin[2 * j], gin[2 * j + 1]);
    } else if (j < N_PTS + M_PTS) {
        int m = j - N_PTS;
        psout[m] = split_u64(gout[2 * m], gout[2 * m + 1]);
    }
}

// ---------------- projection MLP (also writes split f) ----------------
__global__ void proj_kernel(const float* __restrict__ inp,
                            const float* __restrict__ W0, const float* __restrict__ b0,
                            const float* __restrict__ W1, const float* __restrict__ b1,
                            float* __restrict__ f0, u64* __restrict__ fsplit) {
    __shared__ float hs[4][64];
    int warp = threadIdx.x >> 5, lane = threadIdx.x & 31;
    int pv = blockIdx.x * 4 + warp;
    if (pv >= VARS * N_PTS) return;
    int v = pv / N_PTS, n = pv - v * N_PTS;
    const float* x = inp + n * (VARS * 8) + v * 8;
    float xr[8];
#pragma unroll
    for (int i = 0; i < 8; i++) xr[i] = x[i];
    float a0 = b0[lane], a1 = b0[lane + 32];
#pragma unroll
    for (int i = 0; i < 8; i++) {
        a0 = fmaf(xr[i], W0[i * 64 + lane], a0);
        a1 = fmaf(xr[i], W0[i * 64 + lane + 32], a1);
    }
    hs[warp][lane]      = gelu(a0);
    hs[warp][lane + 32] = gelu(a1);
    __syncwarp();
    float acc = b1[lane];
#pragma unroll
    for (int h = 0; h < 64; h++) acc = fmaf(hs[warp][h], W1[h * 32 + lane], acc);
    f0[(size_t)pv * 32 + lane] = acc;
    float accn = __shfl_down_sync(0xffffffffu, acc, 1);
    if (!(lane & 1))
        fsplit[(size_t)pv * 16 + (lane >> 1)] = split_u64(acc, accn);
}

// ---------------- HMMA edge MLP ----------------
// Block: 128 threads = 4 warps; each warp processes 2 tiles of 16 edges.
// Zero shared memory; weights/biases via __ldg; vectored red.global scatter
// with same-segment row merging.
#define TPB 128

template <int MODE>
__global__ void __launch_bounds__(TPB, 4)
edge_mma_kernel(const uint8_t* __restrict__ blob,
                const float* __restrict__ b0g, const float* __restrict__ b1g,
                const float* __restrict__ b2g,
                const u64* __restrict__ psin, const u64* __restrict__ psout,
                const u64* __restrict__ fsplit,
                const int* __restrict__ idxA, const int* __restrict__ idxB,
                float* __restrict__ outbuf, int E) {
    int tid = threadIdx.x;
    int warp = tid >> 5, lane = tid & 31;
    int g = lane >> 2;          // row group 0..7
    int t = lane & 3;           // thread-in-group
    int v = blockIdx.y;

#pragma unroll 1
    for (int mt = 0; mt < 2; mt++) {
        int tileBase = blockIdx.x * 128 + warp * 32 + mt * 16;

        // ---- indices: lanes 0..15 load, all lanes shuffle their rows ----
        int jnv = 0, sgv = -1;
        {
            int e = tileBase + (lane & 15);
            bool gv = e < E;
            int ee = gv ? e : 0;
            if (lane < 16) {
                jnv = __ldg(idxA + ee);
                sgv = gv ? ((MODE == 0) ? __ldg(idxB + ee) : ee / K_LAST) : -1;
            }
        }
        int jn0 = __shfl_sync(0xffffffffu, jnv, g);
        int sg0 = __shfl_sync(0xffffffffu, sgv, g);
        int jn1 = __shfl_sync(0xffffffffu, jnv, g + 8);
        int sg1 = __shfl_sync(0xffffffffu, sgv, g + 8);

        // ---- A1 fragments from pre-split node data ----
        uint32_t a1h[3][4], a1l[3][4];
#pragma unroll
        for (int rs = 0; rs < 2; rs++) {
            int jn = rs ? jn1 : jn0;
            int sg = rs ? sg1 : sg0;
            int sgc = sg < 0 ? 0 : sg;
            const u64* fb = fsplit + ((size_t)v * N_PTS + jn) * 16;
            u64 q00;
            if (t >= 2)      q00 = __ldg(fb + (t - 2));
            else if (t == 0) q00 = __ldg(psin + jn);
            else             q00 = (MODE == 0) ? __ldg(psin + sgc) : __ldg(psout + sgc);
            u64 q01 = __ldg(fb + 2 + t);
            u64 q10 = __ldg(fb + 6 + t);
            u64 q11 = __ldg(fb + 10 + t);
            u64 q20 = (t < 2) ? __ldg(fb + 14 + t) : 0ULL;
            a1h[0][rs]     = (uint32_t)q00; a1l[0][rs]     = (uint32_t)(q00 >> 32);
            a1h[0][rs + 2] = (uint32_t)q01; a1l[0][rs + 2] = (uint32_t)(q01 >> 32);
            a1h[1][rs]     = (uint32_t)q10; a1l[1][rs]     = (uint32_t)(q10 >> 32);
            a1h[1][rs + 2] = (uint32_t)q11; a1l[1][rs + 2] = (uint32_t)(q11 >> 32);
            a1h[2][rs]     = (uint32_t)q20; a1l[2][rs]     = (uint32_t)(q20 >> 32);
            a1h[2][rs + 2] = 0u;            a1l[2][rs + 2] = 0u;
        }

        // ---- layer 1: K=48, N=80 (10 n-tiles), bias folded into init ----
        float d1[10][4];
#pragma unroll
        for (int nt = 0; nt < 10; nt++) {
            float* d = d1[nt];
            float b0f, b1f;
            unpk2(__ldg((const u64*)(b0g + 8 * nt + 2 * t)), b0f, b1f);
            d[0] = b0f; d[1] = b1f; d[2] = b0f; d[3] = b1f;
#pragma unroll
            for (int kt = 0; kt < 3; kt++) {
                int set = kt * 10 + nt;
                uint4 q = __ldg((const uint4*)(blob + BL1 + (size_t)set * 512 + lane * 16));
                mma16816(d, a1h[kt], q.x, q.y);
                mma16816(d, a1h[kt], q.z, q.w);
                mma16816(d, a1l[kt], q.x, q.y);
            }
        }

        // ---- epilogue 1: gelu + split -> A2 fragments ----
        uint32_t a2h[5][4], a2l[5][4];
#pragma unroll
        for (int m = 0; m < 5; m++) {
            int j0 = 2 * m, j1 = 2 * m + 1;
            float q0, q1;
            unpk2(gelu2(pk2(d1[j0][0], d1[j0][1])), q0, q1);
            split_pack(q0, q1, a2h[m][0], a2l[m][0]);
            unpk2(gelu2(pk2(d1[j0][2], d1[j0][3])), q0, q1);
            split_pack(q0, q1, a2h[m][1], a2l[m][1]);
            unpk2(gelu2(pk2(d1[j1][0], d1[j1][1])), q0, q1);
            split_pack(q0, q1, a2h[m][2], a2l[m][2]);
            unpk2(gelu2(pk2(d1[j1][2], d1[j1][3])), q0, q1);
            split_pack(q0, q1, a2h[m][3], a2l[m][3]);
        }

        // ---- layer 2: K=80, N=80 ----
        float d2[10][4];
#pragma unroll
        for (int nt = 0; nt < 10; nt++) {
            float* d = d2[nt];
            float b0f, b1f;
            unpk2(__ldg((const u64*)(b1g + 8 * nt + 2 * t)), b0f, b1f);
            d[0] = b0f; d[1] = b1f; d[2] = b0f; d[3] = b1f;
#pragma unroll
            for (int kt = 0; kt < 5; kt++) {
                int set = kt * 10 + nt;
                uint4 q = __ldg((const uint4*)(blob + BL2 + (size_t)set * 512 + lane * 16));
                mma16816(d, a2h[kt], q.x, q.y);
                mma16816(d, a2h[kt], q.z, q.w);
                mma16816(d, a2l[kt], q.x, q.y);
            }
        }

        // ---- epilogue 2 -> A3 fragments ----
        uint32_t a3h[5][4], a3l[5][4];
#pragma unroll
        for (int m = 0; m < 5; m++) {
            int j0 = 2 * m, j1 = 2 * m + 1;
            float q0, q1;
            unpk2(gelu2(pk2(d2[j0][0], d2[j0][1])), q0, q1);
            split_pack(q0, q1, a3h[m][0], a3l[m][0]);
            unpk2(gelu2(pk2(d2[j0][2], d2[j0][3])), q0, q1);
            split_pack(q0, q1, a3h[m][1], a3l[m][1]);
            unpk2(gelu2(pk2(d2[j1][0], d2[j1][1])), q0, q1);
            split_pack(q0, q1, a3h[m][2], a3l[m][2]);
            unpk2(gelu2(pk2(d2[j1][2], d2[j1][3])), q0, q1);
            split_pack(q0, q1, a3h[m][3], a3l[m][3]);
        }

        // ---- layer 3: K=80, N=32 (4 n-tiles) + vectored scatter ----
        float scale = (MODE == 0) ? 1.0f : 0.1f;
        float* dst0 = nullptr; float* dst1 = nullptr;
        if (MODE == 0) {
            if (sg0 >= 0) dst0 = outbuf + ((size_t)v * N_PTS + sg0) * 32;
            if (sg1 >= 0) dst1 = outbuf + ((size_t)v * N_PTS + sg1) * 32;
        } else {
            if (sg0 >= 0) dst0 = outbuf + (size_t)sg0 * (VARS * 32) + v * 32;
            if (sg1 >= 0) dst1 = outbuf + (size_t)sg1 * (VARS * 32) + v * 32;
        }
        bool merged = (sg0 == sg1) && (sg0 >= 0);
#pragma unroll
        for (int nt = 0; nt < 4; nt++) {
            float d[4];
            float b0f, b1f;
            unpk2(__ldg((const u64*)(b2g + 8 * nt + 2 * t)), b0f, b1f);
            d[0] = b0f; d[1] = b1f; d[2] = b0f; d[3] = b1f;
#pragma unroll
            for (int kt = 0; kt < 5; kt++) {
                int set = kt * 4 + nt;
                uint4 q = __ldg((const uint4*)(blob + BL3 + (size_t)set * 512 + lane * 16));
                mma16816(d, a3h[kt], q.x, q.y);
                mma16816(d, a3h[kt], q.z, q.w);
                mma16816(d, a3l[kt], q.x, q.y);
            }
            int c0 = 8 * nt + 2 * t;
            float s0 = d[0] * scale, s1 = d[1] * scale;
            float s2 = d[2] * scale, s3 = d[3] * scale;
            if (merged) {
                red2(dst0 + c0, s0 + s2, s1 + s3);
            } else {
                if (dst0) red2(dst0 + c0, s0, s1);
                if (dst1) red2(dst1 + c0, s2, s3);
            }
        }
    }
}

// f1 = segment_sum * inv_count + f0 (in place), also refresh fsplit
__global__ void f1_kernel(float* __restrict__ f0, const float* __restrict__ acc,
                          const int* __restrict__ counts, u64* __restrict__ fsplit) {
    int p = blockIdx.x * 256 + threadIdx.x;
    if (p >= VARS * N_PTS * 16) return;
    int n = (p >> 4) % N_PTS;
    int c = counts[n];
    float inv = 1.0f / (float)(c > 1 ? c : 1);
    float a0, a1, fa, fb;
    unpk2(((const u64*)acc)[p], a0, a1);
    unpk2(((const u64*)f0)[p], fa, fb);
    float r0 = fmaf(a0, inv, fa);
    float r1 = fmaf(a1, inv, fb);
    ((u64*)f0)[p] = pk2(r0, r1);
    fsplit[p] = split_u64(r0, r1);
}

extern "C" void kernel_launch(void* const* d_in, const int* in_sizes, int n_in,
                              void* d_out, int out_size) {
    const float* inp   = (const float*)d_in[0];
    const float* gin   = (const float*)d_in[1];
    const float* gout  = (const float*)d_in[2];
    const float* pW0   = (const float*)d_in[3];
    const float* pb0   = (const float*)d_in[4];
    const float* pW1   = (const float*)d_in[5];
    const float* pb1   = (const float*)d_in[6];
    const float* i0W0  = (const float*)d_in[7];
    const float* i0b0  = (const float*)d_in[8];
    const float* i0W1  = (const float*)d_in[9];
    const float* i0b1  = (const float*)d_in[10];
    const float* i0W2  = (const float*)d_in[11];
    const float* i0b2  = (const float*)d_in[12];
    const float* i1W0  = (const float*)d_in[13];
    const float* i1b0  = (const float*)d_in[14];
    const float* i1W1  = (const float*)d_in[15];
    const float* i1b1  = (const float*)d_in[16];
    const float* i1W2  = (const float*)d_in[17];
    const float* i1b2  = (const float*)d_in[18];
    const int* nbr_index  = (const int*)d_in[19];
    const int* nbr_seg    = (const int*)d_in[20];
    const int* nbr_counts = (const int*)d_in[21];
    const int* nbr_last   = (const int*)d_in[22];
    int E = in_sizes[19];

    float *f0, *acc;
    u64 *fsplit, *psin, *psout;
    uint8_t* blob;
    cudaGetSymbolAddress((void**)&f0,     g_f0);
    cudaGetSymbolAddress((void**)&acc,    g_acc);
    cudaGetSymbolAddress((void**)&fsplit, g_fsplit);
    cudaGetSymbolAddress((void**)&psin,   g_psin);
    cudaGetSymbolAddress((void**)&psout,  g_psout);
    cudaGetSymbolAddress((void**)&blob,   g_blob);
    uint8_t* blob0 = blob;
    uint8_t* blob1 = blob + BLOB_BYTES;

    cudaMemsetAsync(acc, 0, sizeof(float) * VARS * N_PTS * 32);
    cudaMemsetAsync(d_out, 0, sizeof(float) * (size_t)out_size);

    // fused prep: weight blobs (both phases) + split positions
    const int PREP_T = 2 * 100 * 32 + N_PTS + M_PTS;
    prep_all_kernel<<<(PREP_T + 255) / 256, 256>>>(i0W0, i0W1, i0W2,
                                                   i1W0, i1W1, i1W2,
                                                   gin, gout, blob0, blob1, psin, psout);

    proj_kernel<<<(VARS * N_PTS + 3) / 4, 128>>>(inp, pW0, pb0, pW1, pb1, f0, fsplit);

    dim3 g1((unsigned)((E + 127) / 128), VARS);
    edge_mma_kernel<0><<<g1, TPB>>>(blob0, i0b0, i0b1, i0b2,
                                    psin, psout, fsplit,
                                    nbr_index, nbr_seg, acc, E);

    f1_kernel<<<(VARS * N_PTS * 16 + 255) / 256, 256>>>(f0, acc, nbr_counts, fsplit);

    int E2 = M_PTS * K_LAST;
    dim3 g2((unsigned)((E2 + 127) / 128), VARS);
    edge_mma_kernel<1><<<g2, TPB>>>(blob1, i1b0, i1b1, i1b2,
                                    psin, psout, fsplit,
                                    nbr_last, nullptr, (float*)d_out, E2);
}